// round 10
// baseline (speedup 1.0000x reference)
#include <cuda_runtime.h>
#include <cuda_bf16.h>
#include <math.h>

// ---------------- device scratch (no allocations allowed) ----------------
__device__ float g_xmean[64];
__device__ float g_attnT[64 * 64];          // TRANSPOSED: attnT[k][c] = attn[c][k]
__device__ float g_p1[32 * 512];            // after conv1+pool
__device__ float g_p2[16 * 256];            // after conv2+pool
__device__ unsigned long long g_bar;        // monotonic ticket counter (never reset)

#define NB 64

// ---------------- K1: fused xmean + per-net MLP -> attn rows (transposed out) -------
__global__ void k_attn2(const float* __restrict__ x,
                        const float* __restrict__ topo,
                        const float* __restrict__ W1,
                        const float* __restrict__ W2) {
    __shared__ float att[64];
    __shared__ float hbuf[128];
    __shared__ float red[8];
    __shared__ unsigned long long s_target;
    __shared__ float wbuf[128 * 65];
    int i = blockIdx.x, t = threadIdx.x;

    {   // own-channel mean
        float4 v = ((const float4*)(x + i * 1024))[t];
        float s = v.x + v.y + v.z + v.w;
        #pragma unroll
        for (int o = 16; o > 0; o >>= 1) s += __shfl_xor_sync(0xffffffffu, s, o);
        if ((t & 31) == 0) red[t >> 5] = s;
        __syncthreads();
        if (t < 8) {
            s = red[t];
            #pragma unroll
            for (int o = 4; o > 0; o >>= 1) s += __shfl_xor_sync(0xffu, s, o);
            if (t == 0) {
                g_xmean[i] = s * (1.0f / 1024.0f);
                __threadfence();
                unsigned long long tk = atomicAdd(&g_bar, 1ULL);
                s_target = (tk / (unsigned long long)NB) * (unsigned long long)NB
                           + (unsigned long long)NB;
            }
        }
    }

    {   // stage W1[i] (128x64) stride 65 — hides the wait
        const float4* W1i = (const float4*)(W1 + i * 8192);
        #pragma unroll
        for (int r = 0; r < 8; r++) {
            int v = t + 256 * r;
            float4 q = W1i[v];
            int e = v * 4;
            int h = e >> 6, k = e & 63;
            float* d = &wbuf[h * 65 + k];
            d[0] = q.x; d[1] = q.y; d[2] = q.z; d[3] = q.w;
        }
    }
    __syncthreads();

    if (t == 0) {
        unsigned long long target = s_target;
        while (*(volatile unsigned long long*)&g_bar < target) { }
        __threadfence();
    }
    __syncthreads();

    if (t < 64) att[t] = g_xmean[t] * topo[i * 64 + t];
    __syncthreads();

    if (t < 128) {
        float s = 0.f;
        const float* wr = &wbuf[t * 65];
        #pragma unroll
        for (int k = 0; k < 64; k++) s += att[k] * wr[k];
        hbuf[t] = fmaxf(s, 0.f);
    }
    __syncthreads();

    {   // stage W2[i] (64x128) stride 129
        const float4* W2i = (const float4*)(W2 + i * 8192);
        #pragma unroll
        for (int r = 0; r < 8; r++) {
            int v = t + 256 * r;
            float4 q = W2i[v];
            int e = v * 4;
            int o = e >> 7, h = e & 127;
            float* d = &wbuf[o * 129 + h];
            d[0] = q.x; d[1] = q.y; d[2] = q.z; d[3] = q.w;
        }
    }
    __syncthreads();

    if (t < 64) {
        float s = 0.f;
        const float* wr = &wbuf[t * 129];
        #pragma unroll
        for (int h = 0; h < 128; h++) s += hbuf[h] * wr[h];
        // transposed: attnT[k=t][c=i]
        g_attnT[t * 64 + i] = 1.0f / (1.0f + __expf(-s));
    }
}

// ---------------- K2: y = attnT^T @ x fused with conv1+relu+pool ----------------
// 64 blocks x 256 threads, 16 prepool positions per tile.
__global__ void k_y_conv1(const float* __restrict__ x,
                          const float* __restrict__ c1_w,
                          const float* __restrict__ c1_b) {
    extern __shared__ __align__(16) float sm[];
    float* attnT = sm;              // 4096 (attnT[k*64+c])
    float* xs    = sm + 4096;       // 64*20
    float* ys    = sm + 5376;       // 64*20
    float* wpad  = sm + 6656;       // 32*64*8 = 16384 (stride-8 padded weights)

    int tile = blockIdx.x, tid = threadIdx.x;
    int l0 = tile * 16 - 2;

    {   // stage attnT float4 copy
        const float4* a4 = (const float4*)g_attnT;
        float4* d4 = (float4*)attnT;
        #pragma unroll
        for (int r = 0; r < 4; r++) d4[tid + 256 * r] = a4[tid + 256 * r];
    }
    for (int s = tid; s < 16384; s += 256) {
        int dt = s & 7;
        wpad[s] = (dt < 5) ? c1_w[(s >> 3) * 5 + dt] : 0.f;
    }
    for (int j = tid; j < 64 * 20; j += 256) {
        int k = j / 20, jj = j - k * 20;
        int gl = l0 + jj;
        xs[j] = ((unsigned)gl < 1024u) ? x[k * 1024 + gl] : 0.f;
    }
    __syncthreads();

    // GEMM: 160 active threads: (cgroup of 8 channels) x (j in 0..19)
    if (tid < 160) {
        int g = tid / 20, j = tid - g * 20;
        int c0 = g * 8;
        float acc0 = 0.f, acc1 = 0.f, acc2 = 0.f, acc3 = 0.f;
        float acc4 = 0.f, acc5 = 0.f, acc6 = 0.f, acc7 = 0.f;
        const float4* aT4 = (const float4*)attnT;
        #pragma unroll 4
        for (int k = 0; k < 64; k++) {
            float xv = xs[k * 20 + j];
            float4 a = aT4[(k << 4) + (c0 >> 2)];
            float4 b = aT4[(k << 4) + (c0 >> 2) + 1];
            acc0 += a.x * xv; acc1 += a.y * xv; acc2 += a.z * xv; acc3 += a.w * xv;
            acc4 += b.x * xv; acc5 += b.y * xv; acc6 += b.z * xv; acc7 += b.w * xv;
        }
        ys[(c0 + 0) * 20 + j] = acc0;
        ys[(c0 + 1) * 20 + j] = acc1;
        ys[(c0 + 2) * 20 + j] = acc2;
        ys[(c0 + 3) * 20 + j] = acc3;
        ys[(c0 + 4) * 20 + j] = acc4;
        ys[(c0 + 5) * 20 + j] = acc5;
        ys[(c0 + 6) * 20 + j] = acc6;
        ys[(c0 + 7) * 20 + j] = acc7;
    }
    __syncthreads();

    // conv1 + relu + pool: 32 oc x 8 pooled; vectorized LDS
    {
        int o = tid >> 3, p = tid & 7;
        float z0 = c1_b[o], z1 = z0;
        const float4* wo4 = (const float4*)&wpad[o * 512];
        for (int c = 0; c < 64; c++) {
            float4 w0 = wo4[c * 2];
            float4 w1 = wo4[c * 2 + 1];   // w1.x = tap4; rest zero
            const float2* pr2 = (const float2*)&ys[c * 20 + 2 * p];
            float2 q0 = pr2[0], q1 = pr2[1], q2 = pr2[2];
            z0 += w0.x * q0.x + w0.y * q0.y + w0.z * q1.x + w0.w * q1.y + w1.x * q2.x;
            z1 += w0.x * q0.y + w0.y * q1.x + w0.z * q1.y + w0.w * q2.x + w1.x * q2.y;
        }
        g_p1[o * 512 + tile * 8 + p] = fmaxf(fmaxf(z0, 0.f), fmaxf(z1, 0.f));
    }
}

// ---------------- K3: conv2 + relu + pool (32,512)->(16,256) ----------------
// 16 blocks x 256 threads (16 oc x 16 pooled).
__global__ void k_conv2(const float* __restrict__ c2_w,
                        const float* __restrict__ c2_b) {
    __shared__ __align__(16) float ps[32 * 36];
    __shared__ __align__(16) float w2p[16 * 32 * 8];   // 4096
    __shared__ float bs[16];
    int tile = blockIdx.x, tid = threadIdx.x;
    int base = tile * 32 - 2;

    for (int s = tid; s < 4096; s += 256) {
        int dt = s & 7;
        w2p[s] = (dt < 5) ? c2_w[(s >> 3) * 5 + dt] : 0.f;
    }
    for (int j = tid; j < 32 * 36; j += 256) {
        int c = j / 36, m = j - c * 36;
        int g = base + m;
        ps[j] = ((unsigned)g < 512u) ? g_p1[c * 512 + g] : 0.f;
    }
    if (tid < 16) bs[tid] = c2_b[tid];
    __syncthreads();

    int o = tid >> 4, pl = tid & 15;
    float z0 = bs[o], z1 = z0;
    const float4* wo4 = (const float4*)&w2p[o * 256];
    for (int c = 0; c < 32; c++) {
        float4 w0 = wo4[c * 2];
        float4 w1 = wo4[c * 2 + 1];
        const float2* pr2 = (const float2*)&ps[c * 36 + 2 * pl];
        float2 q0 = pr2[0], q1 = pr2[1], q2 = pr2[2];
        z0 += w0.x * q0.x + w0.y * q0.y + w0.z * q1.x + w0.w * q1.y + w1.x * q2.x;
        z1 += w0.x * q0.y + w0.y * q1.x + w0.z * q1.y + w0.w * q2.x + w1.x * q2.y;
    }
    g_p2[o * 256 + tile * 16 + pl] = fmaxf(fmaxf(z0, 0.f), fmaxf(z1, 0.f));
}

// ---------------- K4: conv3..conv6 + final linear, 1 block x 1024 threads -----------
// Pad-4 rows with zeroed halos; stride-8 padded weights; float2/float4 LDS.
__global__ void __launch_bounds__(1024, 1)
k_tail(const float* __restrict__ c3_w, const float* __restrict__ c3_b,
       const float* __restrict__ c4_w, const float* __restrict__ c4_b,
       const float* __restrict__ c5_w, const float* __restrict__ c5_b,
       const float* __restrict__ c6_w, const float* __restrict__ c6_b,
       const float* __restrict__ out_w, const float* __restrict__ out_b,
       float* __restrict__ out) {
    __shared__ __align__(16) float s2p[16 * 264];  // payload at +4
    __shared__ __align__(16) float s3p[8 * 136];
    __shared__ __align__(16) float s4p[4 * 72];
    __shared__ __align__(16) float s5p[2 * 40];
    __shared__ float s6[16];
    __shared__ __align__(16) float w3p[1024];      // 8*16*8
    __shared__ __align__(16) float w4p[256];       // 4*8*8
    __shared__ __align__(16) float w5p[64];        // 2*4*8
    __shared__ __align__(16) float w6p[16];        // 1*2*8
    int tid = threadIdx.x;

    // zero padded buffers
    for (int j = tid; j < 16 * 264; j += 1024) s2p[j] = 0.f;
    {
        int tot = 8 * 136 + 4 * 72 + 2 * 40;
        for (int j = tid; j < tot; j += 1024) {
            if (j < 8 * 136) s3p[j] = 0.f;
            else if (j < 8 * 136 + 4 * 72) s4p[j - 8 * 136] = 0.f;
            else s5p[j - 8 * 136 - 4 * 72] = 0.f;
        }
    }
    // stage padded weights
    {
        int dt = tid & 7;
        w3p[tid] = (dt < 5) ? c3_w[(tid >> 3) * 5 + dt] : 0.f;
        if (tid < 256) w4p[tid] = (dt < 5) ? c4_w[(tid >> 3) * 5 + dt] : 0.f;
        else if (tid < 320) { int s = tid - 256; int d2 = s & 7;
            w5p[s] = (d2 < 5) ? c5_w[(s >> 3) * 5 + d2] : 0.f; }
        else if (tid < 336) { int s = tid - 320; int d2 = s & 7;
            w6p[s] = (d2 < 5) ? c6_w[(s >> 3) * 5 + d2] : 0.f; }
    }
    __syncthreads();

    // stage s2 payload via float4 (offset +4 keeps 16B alignment)
    {
        const float4* g4 = (const float4*)g_p2;
        float4 q = g4[tid];
        int c = tid >> 6, pos = (tid & 63) * 4;
        *(float4*)&s2p[c * 264 + 4 + pos] = q;
    }
    __syncthreads();

    // conv3: (16,256)->(8,128), 1024 outputs, 1 pooled/thread
    {
        int o = tid >> 7, p = tid & 127;
        int l = 2 * p;
        float z0 = c3_b[o], z1 = z0;
        const float4* wo4 = (const float4*)&w3p[o * 128];
        for (int c = 0; c < 16; c++) {
            float4 w0 = wo4[c * 2];
            float4 w1 = wo4[c * 2 + 1];
            const float2* pr2 = (const float2*)&s2p[c * 264 + l + 2];
            float2 q0 = pr2[0], q1 = pr2[1], q2 = pr2[2];
            z0 += w0.x * q0.x + w0.y * q0.y + w0.z * q1.x + w0.w * q1.y + w1.x * q2.x;
            z1 += w0.x * q0.y + w0.y * q1.x + w0.z * q1.y + w0.w * q2.x + w1.x * q2.y;
        }
        s3p[o * 136 + 4 + p] = fmaxf(fmaxf(z0, 0.f), fmaxf(z1, 0.f));
    }
    __syncthreads();

    // conv4: (8,128)->(4,64)
    if (tid < 256) {
        int o = tid >> 6, p = tid & 63;
        int l = 2 * p;
        float z0 = c4_b[o], z1 = z0;
        const float4* wo4 = (const float4*)&w4p[o * 64];
        for (int c = 0; c < 8; c++) {
            float4 w0 = wo4[c * 2];
            float4 w1 = wo4[c * 2 + 1];
            const float2* pr2 = (const float2*)&s3p[c * 136 + l + 2];
            float2 q0 = pr2[0], q1 = pr2[1], q2 = pr2[2];
            z0 += w0.x * q0.x + w0.y * q0.y + w0.z * q1.x + w0.w * q1.y + w1.x * q2.x;
            z1 += w0.x * q0.y + w0.y * q1.x + w0.z * q1.y + w0.w * q2.x + w1.x * q2.y;
        }
        s4p[o * 72 + 4 + p] = fmaxf(fmaxf(z0, 0.f), fmaxf(z1, 0.f));
    }
    __syncthreads();

    // conv5: (4,64)->(2,32)
    if (tid < 64) {
        int o = tid >> 5, p = tid & 31;
        int l = 2 * p;
        float z0 = c5_b[o], z1 = z0;
        const float4* wo4 = (const float4*)&w5p[o * 32];
        for (int c = 0; c < 4; c++) {
            float4 w0 = wo4[c * 2];
            float4 w1 = wo4[c * 2 + 1];
            const float2* pr2 = (const float2*)&s4p[c * 72 + l + 2];
            float2 q0 = pr2[0], q1 = pr2[1], q2 = pr2[2];
            z0 += w0.x * q0.x + w0.y * q0.y + w0.z * q1.x + w0.w * q1.y + w1.x * q2.x;
            z1 += w0.x * q0.y + w0.y * q1.x + w0.z * q1.y + w0.w * q2.x + w1.x * q2.y;
        }
        s5p[o * 40 + 4 + p] = fmaxf(fmaxf(z0, 0.f), fmaxf(z1, 0.f));
    }
    __syncthreads();

    // conv6: (2,32)->(1,16)
    if (tid < 16) {
        int l = 2 * tid;
        float z0 = c6_b[0], z1 = z0;
        const float4* wo4 = (const float4*)w6p;
        for (int c = 0; c < 2; c++) {
            float4 w0 = wo4[c * 2];
            float4 w1 = wo4[c * 2 + 1];
            const float2* pr2 = (const float2*)&s5p[c * 40 + l + 2];
            float2 q0 = pr2[0], q1 = pr2[1], q2 = pr2[2];
            z0 += w0.x * q0.x + w0.y * q0.y + w0.z * q1.x + w0.w * q1.y + w1.x * q2.x;
            z1 += w0.x * q0.y + w0.y * q1.x + w0.z * q1.y + w0.w * q2.x + w1.x * q2.y;
        }
        s6[tid] = fmaxf(fmaxf(z0, 0.f), fmaxf(z1, 0.f));
    }
    __syncthreads();

    if (tid == 0) {
        float s = out_b[0];
        #pragma unroll
        for (int j = 0; j < 16; j++) s += s6[j] * out_w[j];
        out[0] = s;
    }
}

extern "C" void kernel_launch(void* const* d_in, const int* in_sizes, int n_in,
                              void* d_out, int out_size) {
    const float* x     = (const float*)d_in[0];
    const float* topo  = (const float*)d_in[1];
    const float* W1    = (const float*)d_in[2];
    const float* W2    = (const float*)d_in[3];
    const float* c1_w  = (const float*)d_in[4];
    const float* c1_b  = (const float*)d_in[5];
    const float* c2_w  = (const float*)d_in[6];
    const float* c2_b  = (const float*)d_in[7];
    const float* c3_w  = (const float*)d_in[8];
    const float* c3_b  = (const float*)d_in[9];
    const float* c4_w  = (const float*)d_in[10];
    const float* c4_b  = (const float*)d_in[11];
    const float* c5_w  = (const float*)d_in[12];
    const float* c5_b  = (const float*)d_in[13];
    const float* c6_w  = (const float*)d_in[14];
    const float* c6_b  = (const float*)d_in[15];
    const float* out_w = (const float*)d_in[16];
    const float* out_b = (const float*)d_in[17];
    float* out = (float*)d_out;

    const int k2_smem = (4096 + 1280 + 1280 + 16384) * 4;   // 92160 B
    cudaFuncSetAttribute(k_y_conv1, cudaFuncAttributeMaxDynamicSharedMemorySize, k2_smem);

    k_attn2<<<NB, 256>>>(x, topo, W1, W2);
    k_y_conv1<<<64, 256, k2_smem>>>(x, c1_w, c1_b);
    k_conv2<<<16, 256>>>(c2_w, c2_b);
    k_tail<<<1, 1024>>>(c3_w, c3_b, c4_w, c4_b, c5_w, c5_b, c6_w, c6_b, out_w, out_b, out);
}

// round 11
// speedup vs baseline: 1.0717x; 1.0717x over previous
#include <cuda_runtime.h>
#include <cuda_bf16.h>
#include <math.h>

// ---------------- device scratch (no allocations allowed) ----------------
__device__ float g_xmean[64];
__device__ float g_attnT[64 * 64];          // TRANSPOSED: attnT[k][c] = attn[c][k]
__device__ float g_p1[32 * 512];            // after conv1+pool
__device__ float g_p2[16 * 256];            // after conv2+pool
__device__ unsigned long long g_bar;        // monotonic ticket counter (never reset)

#define NB 64

// ---------------- K1: fused xmean + per-net MLP (split dots) -> attnT ----------------
__global__ void k_attn2(const float* __restrict__ x,
                        const float* __restrict__ topo,
                        const float* __restrict__ W1,
                        const float* __restrict__ W2) {
    __shared__ float att[64];
    __shared__ float hbuf[128];
    __shared__ float part[256];
    __shared__ float red[8];
    __shared__ unsigned long long s_target;
    __shared__ float wbuf[128 * 65];
    int i = blockIdx.x, t = threadIdx.x;

    {   // own-channel mean
        float4 v = ((const float4*)(x + i * 1024))[t];
        float s = v.x + v.y + v.z + v.w;
        #pragma unroll
        for (int o = 16; o > 0; o >>= 1) s += __shfl_xor_sync(0xffffffffu, s, o);
        if ((t & 31) == 0) red[t >> 5] = s;
        __syncthreads();
        if (t < 8) {
            s = red[t];
            #pragma unroll
            for (int o = 4; o > 0; o >>= 1) s += __shfl_xor_sync(0xffu, s, o);
            if (t == 0) {
                g_xmean[i] = s * (1.0f / 1024.0f);
                __threadfence();
                unsigned long long tk = atomicAdd(&g_bar, 1ULL);
                s_target = (tk / (unsigned long long)NB) * (unsigned long long)NB
                           + (unsigned long long)NB;
            }
        }
    }

    {   // stage W1[i] (128x64) stride 65 — hides the wait for other means
        const float4* W1i = (const float4*)(W1 + i * 8192);
        #pragma unroll
        for (int r = 0; r < 8; r++) {
            int v = t + 256 * r;
            float4 q = W1i[v];
            int e = v * 4;
            int h = e >> 6, k = e & 63;
            float* d = &wbuf[h * 65 + k];
            d[0] = q.x; d[1] = q.y; d[2] = q.z; d[3] = q.w;
        }
    }
    __syncthreads();

    if (t == 0) {
        unsigned long long target = s_target;
        while (*(volatile unsigned long long*)&g_bar < target) { }
        __threadfence();
    }
    __syncthreads();

    if (t < 64) att[t] = g_xmean[t] * topo[i * 64 + t];
    __syncthreads();

    // dot1 split: 256 threads = 128 h x 2 k-halves (chain length 32)
    {
        int h = t & 127, half = t >> 7;
        int k0 = half * 32;
        float s = 0.f;
        const float* wr = &wbuf[h * 65 + k0];
        const float* ar = &att[k0];
        #pragma unroll
        for (int k = 0; k < 32; k++) s += ar[k] * wr[k];
        part[half * 128 + h] = s;
    }
    __syncthreads();
    if (t < 128) hbuf[t] = fmaxf(part[t] + part[128 + t], 0.f);
    __syncthreads();

    {   // stage W2[i] (64x128) stride 129
        const float4* W2i = (const float4*)(W2 + i * 8192);
        #pragma unroll
        for (int r = 0; r < 8; r++) {
            int v = t + 256 * r;
            float4 q = W2i[v];
            int e = v * 4;
            int o = e >> 7, h = e & 127;
            float* d = &wbuf[o * 129 + h];
            d[0] = q.x; d[1] = q.y; d[2] = q.z; d[3] = q.w;
        }
    }
    __syncthreads();

    // dot2 split: 256 threads = 64 o x 4 h-quarters (chain length 32)
    {
        int o = t & 63, q = t >> 6;
        int h0 = q * 32;
        float s = 0.f;
        const float* wr = &wbuf[o * 129 + h0];
        const float* hr = &hbuf[h0];
        #pragma unroll
        for (int h = 0; h < 32; h++) s += hr[h] * wr[h];
        part[q * 64 + o] = s;
    }
    __syncthreads();
    if (t < 64) {
        float s = part[t] + part[64 + t] + part[128 + t] + part[192 + t];
        g_attnT[t * 64 + i] = 1.0f / (1.0f + __expf(-s));
    }
}

// ---------------- K2: y = attnT^T @ x fused with conv1+relu+pool ----------------
// 64 blocks x 256 threads, 16 prepool positions per tile.
__global__ void k_y_conv1(const float* __restrict__ x,
                          const float* __restrict__ c1_w,
                          const float* __restrict__ c1_b) {
    extern __shared__ __align__(16) float sm[];
    float* attnT = sm;              // 4096
    float* xs    = sm + 4096;       // 64*20
    float* ys    = sm + 5376;       // 64*20
    float* wpad  = sm + 6656;       // 16384 (stride-8 padded weights)

    int tile = blockIdx.x, tid = threadIdx.x;
    int l0 = tile * 16 - 2;

    {
        const float4* a4 = (const float4*)g_attnT;
        float4* d4 = (float4*)attnT;
        #pragma unroll
        for (int r = 0; r < 4; r++) d4[tid + 256 * r] = a4[tid + 256 * r];
    }
    for (int s = tid; s < 16384; s += 256) {
        int dt = s & 7;
        wpad[s] = (dt < 5) ? c1_w[(s >> 3) * 5 + dt] : 0.f;
    }
    for (int j = tid; j < 64 * 20; j += 256) {
        int k = j / 20, jj = j - k * 20;
        int gl = l0 + jj;
        xs[j] = ((unsigned)gl < 1024u) ? x[k * 1024 + gl] : 0.f;
    }
    __syncthreads();

    // GEMM: 320 slots = 16 groups (4ch) x 20 j, over 256 threads
    for (int idx = tid; idx < 320; idx += 256) {
        int g = idx / 20, j = idx - g * 20;
        float a0 = 0.f, a1 = 0.f, a2 = 0.f, a3 = 0.f;
        const float4* aT4 = (const float4*)attnT;
        #pragma unroll 4
        for (int k = 0; k < 64; k++) {
            float xv = xs[k * 20 + j];
            float4 a = aT4[(k << 4) + g];
            a0 += a.x * xv; a1 += a.y * xv; a2 += a.z * xv; a3 += a.w * xv;
        }
        int c0 = g * 4;
        ys[(c0 + 0) * 20 + j] = a0;
        ys[(c0 + 1) * 20 + j] = a1;
        ys[(c0 + 2) * 20 + j] = a2;
        ys[(c0 + 3) * 20 + j] = a3;
    }
    __syncthreads();

    // conv1 + relu + pool: 32 oc x 8 pooled; dual accumulator chains
    {
        int o = tid >> 3, p = tid & 7;
        float z0a = c1_b[o], z1a = z0a, z0b = 0.f, z1b = 0.f;
        const float4* wo4 = (const float4*)&wpad[o * 512];
        for (int c = 0; c < 64; c += 2) {
            {
                float4 w0 = wo4[c * 2];
                float4 w1 = wo4[c * 2 + 1];
                const float2* pr2 = (const float2*)&ys[c * 20 + 2 * p];
                float2 q0 = pr2[0], q1 = pr2[1], q2 = pr2[2];
                z0a += w0.x * q0.x + w0.y * q0.y + w0.z * q1.x + w0.w * q1.y + w1.x * q2.x;
                z1a += w0.x * q0.y + w0.y * q1.x + w0.z * q1.y + w0.w * q2.x + w1.x * q2.y;
            }
            {
                float4 w0 = wo4[(c + 1) * 2];
                float4 w1 = wo4[(c + 1) * 2 + 1];
                const float2* pr2 = (const float2*)&ys[(c + 1) * 20 + 2 * p];
                float2 q0 = pr2[0], q1 = pr2[1], q2 = pr2[2];
                z0b += w0.x * q0.x + w0.y * q0.y + w0.z * q1.x + w0.w * q1.y + w1.x * q2.x;
                z1b += w0.x * q0.y + w0.y * q1.x + w0.z * q1.y + w0.w * q2.x + w1.x * q2.y;
            }
        }
        float z0 = z0a + z0b, z1 = z1a + z1b;
        g_p1[o * 512 + tile * 8 + p] = fmaxf(fmaxf(z0, 0.f), fmaxf(z1, 0.f));
    }
}

// ---------------- K3: conv2 + relu + pool (32,512)->(16,256) ----------------
__global__ void k_conv2(const float* __restrict__ c2_w,
                        const float* __restrict__ c2_b) {
    __shared__ __align__(16) float ps[32 * 36];
    __shared__ __align__(16) float w2p[16 * 32 * 8];
    __shared__ float bs[16];
    int tile = blockIdx.x, tid = threadIdx.x;
    int base = tile * 32 - 2;

    for (int s = tid; s < 4096; s += 256) {
        int dt = s & 7;
        w2p[s] = (dt < 5) ? c2_w[(s >> 3) * 5 + dt] : 0.f;
    }
    for (int j = tid; j < 32 * 36; j += 256) {
        int c = j / 36, m = j - c * 36;
        int g = base + m;
        ps[j] = ((unsigned)g < 512u) ? g_p1[c * 512 + g] : 0.f;
    }
    if (tid < 16) bs[tid] = c2_b[tid];
    __syncthreads();

    int o = tid >> 4, pl = tid & 15;
    float z0a = bs[o], z1a = z0a, z0b = 0.f, z1b = 0.f;
    const float4* wo4 = (const float4*)&w2p[o * 256];
    for (int c = 0; c < 32; c += 2) {
        {
            float4 w0 = wo4[c * 2];
            float4 w1 = wo4[c * 2 + 1];
            const float2* pr2 = (const float2*)&ps[c * 36 + 2 * pl];
            float2 q0 = pr2[0], q1 = pr2[1], q2 = pr2[2];
            z0a += w0.x * q0.x + w0.y * q0.y + w0.z * q1.x + w0.w * q1.y + w1.x * q2.x;
            z1a += w0.x * q0.y + w0.y * q1.x + w0.z * q1.y + w0.w * q2.x + w1.x * q2.y;
        }
        {
            float4 w0 = wo4[(c + 1) * 2];
            float4 w1 = wo4[(c + 1) * 2 + 1];
            const float2* pr2 = (const float2*)&ps[(c + 1) * 36 + 2 * pl];
            float2 q0 = pr2[0], q1 = pr2[1], q2 = pr2[2];
            z0b += w0.x * q0.x + w0.y * q0.y + w0.z * q1.x + w0.w * q1.y + w1.x * q2.x;
            z1b += w0.x * q0.y + w0.y * q1.x + w0.z * q1.y + w0.w * q2.x + w1.x * q2.y;
        }
    }
    float z0 = z0a + z0b, z1 = z1a + z1b;
    g_p2[o * 256 + tile * 16 + pl] = fmaxf(fmaxf(z0, 0.f), fmaxf(z1, 0.f));
}

// ---------------- K4: conv3..conv6 + final linear, 1 block x 1024 threads -----------
__global__ void __launch_bounds__(1024, 1)
k_tail(const float* __restrict__ c3_w, const float* __restrict__ c3_b,
       const float* __restrict__ c4_w, const float* __restrict__ c4_b,
       const float* __restrict__ c5_w, const float* __restrict__ c5_b,
       const float* __restrict__ c6_w, const float* __restrict__ c6_b,
       const float* __restrict__ out_w, const float* __restrict__ out_b,
       float* __restrict__ out) {
    __shared__ __align__(16) float s2p[16 * 264];  // payload at +4
    __shared__ __align__(16) float s3p[8 * 136];
    __shared__ __align__(16) float s4p[4 * 72];
    __shared__ __align__(16) float s5p[2 * 40];
    __shared__ float s6[16];
    __shared__ __align__(16) float w3p[1024];
    __shared__ __align__(16) float w4p[256];
    __shared__ __align__(16) float w5p[64];
    __shared__ __align__(16) float w6p[16];
    int tid = threadIdx.x;

    // zero ONLY halos: s2p 16x(4+4), s3p 8x(4+4), s4p 4x(4+4), s5p 2x(4+4) = 240 words
    if (tid < 240) {
        int j = tid;
        if (j < 128) {                 // s2p: row j>>3, word j&7 (0-3 lo, 4-7 hi)
            int r = j >> 3, w = j & 7;
            s2p[r * 264 + ((w < 4) ? w : 256 + w)] = 0.f;
        } else if (j < 192) {
            int s = j - 128; int r = s >> 3, w = s & 7;
            s3p[r * 136 + ((w < 4) ? w : 128 + w)] = 0.f;
        } else if (j < 224) {
            int s = j - 192; int r = s >> 3, w = s & 7;
            s4p[r * 72 + ((w < 4) ? w : 64 + w)] = 0.f;
        } else {
            int s = j - 224; int r = s >> 3, w = s & 7;
            s5p[r * 40 + ((w < 4) ? w : 32 + w)] = 0.f;
        }
    }
    // stage padded weights
    {
        int dt = tid & 7;
        w3p[tid] = (dt < 5) ? c3_w[(tid >> 3) * 5 + dt] : 0.f;
        if (tid < 256) w4p[tid] = (dt < 5) ? c4_w[(tid >> 3) * 5 + dt] : 0.f;
        else if (tid < 320) { int s = tid - 256; int d2 = s & 7;
            w5p[s] = (d2 < 5) ? c5_w[(s >> 3) * 5 + d2] : 0.f; }
        else if (tid < 336) { int s = tid - 320; int d2 = s & 7;
            w6p[s] = (d2 < 5) ? c6_w[(s >> 3) * 5 + d2] : 0.f; }
    }
    // stage s2 payload via float4
    {
        const float4* g4 = (const float4*)g_p2;
        float4 q = g4[tid];
        int c = tid >> 6, pos = (tid & 63) * 4;
        *(float4*)&s2p[c * 264 + 4 + pos] = q;
    }
    __syncthreads();

    // conv3: (16,256)->(8,128), 1/thread; dual chains
    {
        int o = tid >> 7, p = tid & 127;
        int l = 2 * p;
        float z0a = c3_b[o], z1a = z0a, z0b = 0.f, z1b = 0.f;
        const float4* wo4 = (const float4*)&w3p[o * 128];
        for (int c = 0; c < 16; c += 2) {
            {
                float4 w0 = wo4[c * 2];
                float4 w1 = wo4[c * 2 + 1];
                const float2* pr2 = (const float2*)&s2p[c * 264 + l + 2];
                float2 q0 = pr2[0], q1 = pr2[1], q2 = pr2[2];
                z0a += w0.x * q0.x + w0.y * q0.y + w0.z * q1.x + w0.w * q1.y + w1.x * q2.x;
                z1a += w0.x * q0.y + w0.y * q1.x + w0.z * q1.y + w0.w * q2.x + w1.x * q2.y;
            }
            {
                float4 w0 = wo4[(c + 1) * 2];
                float4 w1 = wo4[(c + 1) * 2 + 1];
                const float2* pr2 = (const float2*)&s2p[(c + 1) * 264 + l + 2];
                float2 q0 = pr2[0], q1 = pr2[1], q2 = pr2[2];
                z0b += w0.x * q0.x + w0.y * q0.y + w0.z * q1.x + w0.w * q1.y + w1.x * q2.x;
                z1b += w0.x * q0.y + w0.y * q1.x + w0.z * q1.y + w0.w * q2.x + w1.x * q2.y;
            }
        }
        float z0 = z0a + z0b, z1 = z1a + z1b;
        s3p[o * 136 + 4 + p] = fmaxf(fmaxf(z0, 0.f), fmaxf(z1, 0.f));
    }
    __syncthreads();

    // conv4: (8,128)->(4,64); dual chains
    if (tid < 256) {
        int o = tid >> 6, p = tid & 63;
        int l = 2 * p;
        float z0a = c4_b[o], z1a = z0a, z0b = 0.f, z1b = 0.f;
        const float4* wo4 = (const float4*)&w4p[o * 64];
        for (int c = 0; c < 8; c += 2) {
            {
                float4 w0 = wo4[c * 2];
                float4 w1 = wo4[c * 2 + 1];
                const float2* pr2 = (const float2*)&s3p[c * 136 + l + 2];
                float2 q0 = pr2[0], q1 = pr2[1], q2 = pr2[2];
                z0a += w0.x * q0.x + w0.y * q0.y + w0.z * q1.x + w0.w * q1.y + w1.x * q2.x;
                z1a += w0.x * q0.y + w0.y * q1.x + w0.z * q1.y + w0.w * q2.x + w1.x * q2.y;
            }
            {
                float4 w0 = wo4[(c + 1) * 2];
                float4 w1 = wo4[(c + 1) * 2 + 1];
                const float2* pr2 = (const float2*)&s3p[(c + 1) * 136 + l + 2];
                float2 q0 = pr2[0], q1 = pr2[1], q2 = pr2[2];
                z0b += w0.x * q0.x + w0.y * q0.y + w0.z * q1.x + w0.w * q1.y + w1.x * q2.x;
                z1b += w0.x * q0.y + w0.y * q1.x + w0.z * q1.y + w0.w * q2.x + w1.x * q2.y;
            }
        }
        float z0 = z0a + z0b, z1 = z1a + z1b;
        s4p[o * 72 + 4 + p] = fmaxf(fmaxf(z0, 0.f), fmaxf(z1, 0.f));
    }
    __syncthreads();

    // conv5: (4,64)->(2,32)
    if (tid < 64) {
        int o = tid >> 5, p = tid & 31;
        int l = 2 * p;
        float z0 = c5_b[o], z1 = z0;
        const float4* wo4 = (const float4*)&w5p[o * 32];
        for (int c = 0; c < 4; c++) {
            float4 w0 = wo4[c * 2];
            float4 w1 = wo4[c * 2 + 1];
            const float2* pr2 = (const float2*)&s4p[c * 72 + l + 2];
            float2 q0 = pr2[0], q1 = pr2[1], q2 = pr2[2];
            z0 += w0.x * q0.x + w0.y * q0.y + w0.z * q1.x + w0.w * q1.y + w1.x * q2.x;
            z1 += w0.x * q0.y + w0.y * q1.x + w0.z * q1.y + w0.w * q2.x + w1.x * q2.y;
        }
        s5p[o * 40 + 4 + p] = fmaxf(fmaxf(z0, 0.f), fmaxf(z1, 0.f));
    }
    __syncthreads();

    // conv6: (2,32)->(1,16)
    if (tid < 16) {
        int l = 2 * tid;
        float z0 = c6_b[0], z1 = z0;
        const float4* wo4 = (const float4*)w6p;
        for (int c = 0; c < 2; c++) {
            float4 w0 = wo4[c * 2];
            float4 w1 = wo4[c * 2 + 1];
            const float2* pr2 = (const float2*)&s5p[c * 40 + l + 2];
            float2 q0 = pr2[0], q1 = pr2[1], q2 = pr2[2];
            z0 += w0.x * q0.x + w0.y * q0.y + w0.z * q1.x + w0.w * q1.y + w1.x * q2.x;
            z1 += w0.x * q0.y + w0.y * q1.x + w0.z * q1.y + w0.w * q2.x + w1.x * q2.y;
        }
        s6[tid] = fmaxf(fmaxf(z0, 0.f), fmaxf(z1, 0.f));
    }
    __syncthreads();

    if (tid == 0) {
        float s = out_b[0];
        #pragma unroll
        for (int j = 0; j < 16; j++) s += s6[j] * out_w[j];
        out[0] = s;
    }
}

extern "C" void kernel_launch(void* const* d_in, const int* in_sizes, int n_in,
                              void* d_out, int out_size) {
    const float* x     = (const float*)d_in[0];
    const float* topo  = (const float*)d_in[1];
    const float* W1    = (const float*)d_in[2];
    const float* W2    = (const float*)d_in[3];
    const float* c1_w  = (const float*)d_in[4];
    const float* c1_b  = (const float*)d_in[5];
    const float* c2_w  = (const float*)d_in[6];
    const float* c2_b  = (const float*)d_in[7];
    const float* c3_w  = (const float*)d_in[8];
    const float* c3_b  = (const float*)d_in[9];
    const float* c4_w  = (const float*)d_in[10];
    const float* c4_b  = (const float*)d_in[11];
    const float* c5_w  = (const float*)d_in[12];
    const float* c5_b  = (const float*)d_in[13];
    const float* c6_w  = (const float*)d_in[14];
    const float* c6_b  = (const float*)d_in[15];
    const float* out_w = (const float*)d_in[16];
    const float* out_b = (const float*)d_in[17];
    float* out = (float*)d_out;

    const int k2_smem = (4096 + 1280 + 1280 + 16384) * 4;   // 92160 B
    cudaFuncSetAttribute(k_y_conv1, cudaFuncAttributeMaxDynamicSharedMemorySize, k2_smem);

    k_attn2<<<NB, 256>>>(x, topo, W1, W2);
    k_y_conv1<<<64, 256, k2_smem>>>(x, c1_w, c1_b);
    k_conv2<<<16, 256>>>(c2_w, c2_b);
    k_tail<<<1, 1024>>>(c3_w, c3_b, c4_w, c4_b, c5_w, c5_b, c6_w, c6_b, out_w, out_b, out);
}

// round 12
// speedup vs baseline: 1.2542x; 1.1703x over previous
#include <cuda_runtime.h>
#include <cuda_bf16.h>
#include <math.h>

// ---------------- device scratch (no allocations allowed) ----------------
__device__ float g_xmean[64];
__device__ float g_attnT[64 * 64];          // TRANSPOSED: attnT[k][c] = attn[c][k]
__device__ float g_p1[32 * 512];            // after conv1+pool
__device__ float g_p2[16 * 256];            // after conv2+pool
__device__ float g_p3[8 * 128];             // after conv3+pool
__device__ __align__(16) float g_wpad[21840];  // stride-8 padded conv weights
__device__ unsigned long long g_bar;        // monotonic ticket counter (never reset)

#define NB 64
// g_wpad layout (all rows stride-8, taps 0..4 then zeros):
#define W1PAD 0        // 32*64*8 = 16384
#define W2PAD 16384    // 16*32*8 = 4096
#define W3PAD 20480    // 8*16*8  = 1024
#define W4PAD 21504    // 4*8*8   = 256
#define W5PAD 21760    // 2*4*8   = 64
#define W6PAD 21824    // 1*2*8   = 16

// ---------------- K1: xmean + weight pre-pad + per-net MLP -> attnT ----------------
__global__ void k_attn2(const float* __restrict__ x,
                        const float* __restrict__ topo,
                        const float* __restrict__ W1,
                        const float* __restrict__ W2,
                        const float* __restrict__ c1_w, const float* __restrict__ c2_w,
                        const float* __restrict__ c3_w, const float* __restrict__ c4_w,
                        const float* __restrict__ c5_w, const float* __restrict__ c6_w) {
    __shared__ float att[64];
    __shared__ float hbuf[128];
    __shared__ float part[256];
    __shared__ float red[8];
    __shared__ unsigned long long s_target;
    __shared__ float wbuf[128 * 65];
    int i = blockIdx.x, t = threadIdx.x;

    {   // own-channel mean
        float4 v = ((const float4*)(x + i * 1024))[t];
        float s = v.x + v.y + v.z + v.w;
        #pragma unroll
        for (int o = 16; o > 0; o >>= 1) s += __shfl_xor_sync(0xffffffffu, s, o);
        if ((t & 31) == 0) red[t >> 5] = s;
        __syncthreads();
        if (t < 8) {
            s = red[t];
            #pragma unroll
            for (int o = 4; o > 0; o >>= 1) s += __shfl_xor_sync(0xffu, s, o);
            if (t == 0) {
                g_xmean[i] = s * (1.0f / 1024.0f);
                __threadfence();
                unsigned long long tk = atomicAdd(&g_bar, 1ULL);
                s_target = (tk / (unsigned long long)NB) * (unsigned long long)NB
                           + (unsigned long long)NB;
            }
        }
    }

    // --- pre-pad conv weights into g_wpad (grid-cooperative, ~2 words/thread) ---
    {
        int g = i * 256 + t;
        for (int j = g; j < 21840; j += NB * 256) {
            int row = j >> 3, dt = j & 7;
            float v = 0.f;
            if (dt < 5) {
                if (row < 2048)      v = c1_w[row * 5 + dt];
                else if (row < 2560) v = c2_w[(row - 2048) * 5 + dt];
                else if (row < 2688) v = c3_w[(row - 2560) * 5 + dt];
                else if (row < 2720) v = c4_w[(row - 2688) * 5 + dt];
                else if (row < 2728) v = c5_w[(row - 2720) * 5 + dt];
                else                 v = c6_w[(row - 2728) * 5 + dt];
            }
            g_wpad[j] = v;
        }
    }

    {   // stage W1[i] (128x64) stride 65 — hides the wait for other means
        const float4* W1i = (const float4*)(W1 + i * 8192);
        #pragma unroll
        for (int r = 0; r < 8; r++) {
            int v = t + 256 * r;
            float4 q = W1i[v];
            int e = v * 4;
            int h = e >> 6, k = e & 63;
            float* d = &wbuf[h * 65 + k];
            d[0] = q.x; d[1] = q.y; d[2] = q.z; d[3] = q.w;
        }
    }
    __syncthreads();

    if (t == 0) {
        unsigned long long target = s_target;
        while (*(volatile unsigned long long*)&g_bar < target) { }
        __threadfence();
    }
    __syncthreads();

    if (t < 64) att[t] = g_xmean[t] * topo[i * 64 + t];
    __syncthreads();

    // dot1 split: 128 h x 2 k-halves
    {
        int h = t & 127, half = t >> 7;
        int k0 = half * 32;
        float s = 0.f;
        const float* wr = &wbuf[h * 65 + k0];
        const float* ar = &att[k0];
        #pragma unroll
        for (int k = 0; k < 32; k++) s += ar[k] * wr[k];
        part[half * 128 + h] = s;
    }
    __syncthreads();
    if (t < 128) hbuf[t] = fmaxf(part[t] + part[128 + t], 0.f);
    __syncthreads();

    {   // stage W2[i] (64x128) stride 129
        const float4* W2i = (const float4*)(W2 + i * 8192);
        #pragma unroll
        for (int r = 0; r < 8; r++) {
            int v = t + 256 * r;
            float4 q = W2i[v];
            int e = v * 4;
            int o = e >> 7, h = e & 127;
            float* d = &wbuf[o * 129 + h];
            d[0] = q.x; d[1] = q.y; d[2] = q.z; d[3] = q.w;
        }
    }
    __syncthreads();

    // dot2 split: 64 o x 4 h-quarters
    {
        int o = t & 63, q = t >> 6;
        int h0 = q * 32;
        float s = 0.f;
        const float* wr = &wbuf[o * 129 + h0];
        const float* hr = &hbuf[h0];
        #pragma unroll
        for (int h = 0; h < 32; h++) s += hr[h] * wr[h];
        part[q * 64 + o] = s;
    }
    __syncthreads();
    if (t < 64) {
        float s = part[t] + part[64 + t] + part[128 + t] + part[192 + t];
        g_attnT[t * 64 + i] = 1.0f / (1.0f + __expf(-s));
    }
}

// ---------------- K2: y = attnT^T @ x fused with conv1+relu+pool ----------------
__global__ void k_y_conv1(const float* __restrict__ x,
                          const float* __restrict__ c1_b) {
    extern __shared__ __align__(16) float sm[];
    float* attnT = sm;              // 4096
    float* xs    = sm + 4096;       // 1280
    float* ys    = sm + 5376;       // 1280
    float* wpad  = sm + 6656;       // 16384

    int tile = blockIdx.x, tid = threadIdx.x;
    int l0 = tile * 16 - 2;

    {
        const float4* a4 = (const float4*)g_attnT;
        float4* d4 = (float4*)attnT;
        #pragma unroll
        for (int r = 0; r < 4; r++) d4[tid + 256 * r] = a4[tid + 256 * r];
    }
    {   // padded weights: pure float4 copy (4096 float4, 16/thread)
        const float4* w4 = (const float4*)&g_wpad[W1PAD];
        float4* d4 = (float4*)wpad;
        #pragma unroll
        for (int r = 0; r < 16; r++) d4[tid + 256 * r] = w4[tid + 256 * r];
    }
    for (int j = tid; j < 64 * 20; j += 256) {
        int k = j / 20, jj = j - k * 20;
        int gl = l0 + jj;
        xs[j] = ((unsigned)gl < 1024u) ? x[k * 1024 + gl] : 0.f;
    }
    __syncthreads();

    // GEMM: 320 slots = 16 groups (4ch) x 20 j
    for (int idx = tid; idx < 320; idx += 256) {
        int g = idx / 20, j = idx - g * 20;
        float a0 = 0.f, a1 = 0.f, a2 = 0.f, a3 = 0.f;
        const float4* aT4 = (const float4*)attnT;
        #pragma unroll 4
        for (int k = 0; k < 64; k++) {
            float xv = xs[k * 20 + j];
            float4 a = aT4[(k << 4) + g];
            a0 += a.x * xv; a1 += a.y * xv; a2 += a.z * xv; a3 += a.w * xv;
        }
        int c0 = g * 4;
        ys[(c0 + 0) * 20 + j] = a0;
        ys[(c0 + 1) * 20 + j] = a1;
        ys[(c0 + 2) * 20 + j] = a2;
        ys[(c0 + 3) * 20 + j] = a3;
    }
    __syncthreads();

    // conv1 + relu + pool: 32 oc x 8 pooled; dual chains
    {
        int o = tid >> 3, p = tid & 7;
        float z0a = c1_b[o], z1a = z0a, z0b = 0.f, z1b = 0.f;
        const float4* wo4 = (const float4*)&wpad[o * 512];
        for (int c = 0; c < 64; c += 2) {
            {
                float4 w0 = wo4[c * 2];
                float4 w1 = wo4[c * 2 + 1];
                const float2* pr2 = (const float2*)&ys[c * 20 + 2 * p];
                float2 q0 = pr2[0], q1 = pr2[1], q2 = pr2[2];
                z0a += w0.x * q0.x + w0.y * q0.y + w0.z * q1.x + w0.w * q1.y + w1.x * q2.x;
                z1a += w0.x * q0.y + w0.y * q1.x + w0.z * q1.y + w0.w * q2.x + w1.x * q2.y;
            }
            {
                float4 w0 = wo4[(c + 1) * 2];
                float4 w1 = wo4[(c + 1) * 2 + 1];
                const float2* pr2 = (const float2*)&ys[(c + 1) * 20 + 2 * p];
                float2 q0 = pr2[0], q1 = pr2[1], q2 = pr2[2];
                z0b += w0.x * q0.x + w0.y * q0.y + w0.z * q1.x + w0.w * q1.y + w1.x * q2.x;
                z1b += w0.x * q0.y + w0.y * q1.x + w0.z * q1.y + w0.w * q2.x + w1.x * q2.y;
            }
        }
        float z0 = z0a + z0b, z1 = z1a + z1b;
        g_p1[o * 512 + tile * 8 + p] = fmaxf(fmaxf(z0, 0.f), fmaxf(z1, 0.f));
    }
}

// ---------------- K3: conv2 + relu + pool (32,512)->(16,256) ----------------
__global__ void k_conv2(const float* __restrict__ c2_b) {
    __shared__ __align__(16) float ps[32 * 36];
    __shared__ __align__(16) float w2p[4096];
    __shared__ float bs[16];
    int tile = blockIdx.x, tid = threadIdx.x;
    int base = tile * 32 - 2;

    {   // padded weights: float4 copy (1024 float4, 4/thread)
        const float4* w4 = (const float4*)&g_wpad[W2PAD];
        float4* d4 = (float4*)w2p;
        #pragma unroll
        for (int r = 0; r < 4; r++) d4[tid + 256 * r] = w4[tid + 256 * r];
    }
    for (int j = tid; j < 32 * 36; j += 256) {
        int c = j / 36, m = j - c * 36;
        int g = base + m;
        ps[j] = ((unsigned)g < 512u) ? g_p1[c * 512 + g] : 0.f;
    }
    if (tid < 16) bs[tid] = c2_b[tid];
    __syncthreads();

    int o = tid >> 4, pl = tid & 15;
    float z0a = bs[o], z1a = z0a, z0b = 0.f, z1b = 0.f;
    const float4* wo4 = (const float4*)&w2p[o * 256];
    for (int c = 0; c < 32; c += 2) {
        {
            float4 w0 = wo4[c * 2];
            float4 w1 = wo4[c * 2 + 1];
            const float2* pr2 = (const float2*)&ps[c * 36 + 2 * pl];
            float2 q0 = pr2[0], q1 = pr2[1], q2 = pr2[2];
            z0a += w0.x * q0.x + w0.y * q0.y + w0.z * q1.x + w0.w * q1.y + w1.x * q2.x;
            z1a += w0.x * q0.y + w0.y * q1.x + w0.z * q1.y + w0.w * q2.x + w1.x * q2.y;
        }
        {
            float4 w0 = wo4[(c + 1) * 2];
            float4 w1 = wo4[(c + 1) * 2 + 1];
            const float2* pr2 = (const float2*)&ps[(c + 1) * 36 + 2 * pl];
            float2 q0 = pr2[0], q1 = pr2[1], q2 = pr2[2];
            z0b += w0.x * q0.x + w0.y * q0.y + w0.z * q1.x + w0.w * q1.y + w1.x * q2.x;
            z1b += w0.x * q0.y + w0.y * q1.x + w0.z * q1.y + w0.w * q2.x + w1.x * q2.y;
        }
    }
    float z0 = z0a + z0b, z1 = z1a + z1b;
    g_p2[o * 256 + tile * 16 + pl] = fmaxf(fmaxf(z0, 0.f), fmaxf(z1, 0.f));
}

// ---------------- K4: conv3 (16,256)->(8,128), 8 blocks (1 oc each) ----------------
__global__ void k_conv3(const float* __restrict__ c3_b) {
    __shared__ __align__(16) float s2p[16 * 264];   // pad-4 rows
    __shared__ __align__(16) float w3o[128];        // own oc, 16 ch x 8
    __shared__ float part[2 * 128 * 2];
    int o = blockIdx.x, tid = threadIdx.x;

    // zero halos: 16 rows x 8 words
    if (tid < 128) {
        int r = tid >> 3, w = tid & 7;
        s2p[r * 264 + ((w < 4) ? w : 256 + w)] = 0.f;
    }
    // stage p2 payload via float4 (1024 float4, 4/thread)
    {
        const float4* g4 = (const float4*)g_p2;
        #pragma unroll
        for (int r = 0; r < 4; r++) {
            int v = tid + 256 * r;
            float4 q = g4[v];
            int c = v >> 6, pos = (v & 63) * 4;
            *(float4*)&s2p[c * 264 + 4 + pos] = q;
        }
    }
    if (tid < 32) ((float4*)w3o)[tid] = ((const float4*)&g_wpad[W3PAD + o * 128])[tid];
    __syncthreads();

    // 256 threads = 128 positions x 2 channel-halves (8 ch each)
    {
        int p = tid & 127, h = tid >> 7;
        int c0 = h * 8, l = 2 * p;
        float z0a = (h == 0) ? c3_b[o] : 0.f, z1a = z0a, z0b = 0.f, z1b = 0.f;
        const float4* wo4 = (const float4*)&w3o[c0 * 8];
        for (int c = 0; c < 8; c += 2) {
            {
                float4 w0 = wo4[c * 2];
                float4 w1 = wo4[c * 2 + 1];
                const float2* pr2 = (const float2*)&s2p[(c0 + c) * 264 + l + 2];
                float2 q0 = pr2[0], q1 = pr2[1], q2 = pr2[2];
                z0a += w0.x * q0.x + w0.y * q0.y + w0.z * q1.x + w0.w * q1.y + w1.x * q2.x;
                z1a += w0.x * q0.y + w0.y * q1.x + w0.z * q1.y + w0.w * q2.x + w1.x * q2.y;
            }
            {
                float4 w0 = wo4[(c + 1) * 2];
                float4 w1 = wo4[(c + 1) * 2 + 1];
                const float2* pr2 = (const float2*)&s2p[(c0 + c + 1) * 264 + l + 2];
                float2 q0 = pr2[0], q1 = pr2[1], q2 = pr2[2];
                z0b += w0.x * q0.x + w0.y * q0.y + w0.z * q1.x + w0.w * q1.y + w1.x * q2.x;
                z1b += w0.x * q0.y + w0.y * q1.x + w0.z * q1.y + w0.w * q2.x + w1.x * q2.y;
            }
        }
        part[(h * 128 + p) * 2 + 0] = z0a + z0b;
        part[(h * 128 + p) * 2 + 1] = z1a + z1b;
    }
    __syncthreads();

    if (tid < 128) {
        float z0 = part[tid * 2] + part[(128 + tid) * 2];
        float z1 = part[tid * 2 + 1] + part[(128 + tid) * 2 + 1];
        g_p3[o * 128 + tid] = fmaxf(fmaxf(z0, 0.f), fmaxf(z1, 0.f));
    }
}

// ---------------- K5: conv4..conv6 + final linear, 1 block x 256 threads ------------
__global__ void k_tail2(const float* __restrict__ c4_b,
                        const float* __restrict__ c5_b,
                        const float* __restrict__ c6_b,
                        const float* __restrict__ out_w, const float* __restrict__ out_b,
                        float* __restrict__ out) {
    __shared__ __align__(16) float s3p[8 * 136];
    __shared__ __align__(16) float s4p[4 * 72];
    __shared__ __align__(16) float s5p[2 * 40];
    __shared__ float s6[16];
    __shared__ __align__(16) float w4p[256];
    __shared__ __align__(16) float w5p[64];
    __shared__ __align__(16) float w6p[16];
    int tid = threadIdx.x;

    // zero halos: s3p 64, s4p 32, s5p 16 = 112 words
    if (tid < 112) {
        int j = tid;
        if (j < 64) { int r = j >> 3, w = j & 7;
            s3p[r * 136 + ((w < 4) ? w : 128 + w)] = 0.f; }
        else if (j < 96) { int s = j - 64; int r = s >> 3, w = s & 7;
            s4p[r * 72 + ((w < 4) ? w : 64 + w)] = 0.f; }
        else { int s = j - 96; int r = s >> 3, w = s & 7;
            s5p[r * 40 + ((w < 4) ? w : 32 + w)] = 0.f; }
    }
    // stage p3 payload: 256 float4, 1/thread
    {
        float4 q = ((const float4*)g_p3)[tid];
        int c = tid >> 5, pos = (tid & 31) * 4;
        *(float4*)&s3p[c * 136 + 4 + pos] = q;
    }
    // stage padded weights from g_wpad
    if (tid < 64) ((float4*)w4p)[tid] = ((const float4*)&g_wpad[W4PAD])[tid];
    else if (tid < 80) ((float4*)w5p)[tid - 64] = ((const float4*)&g_wpad[W5PAD])[tid - 64];
    else if (tid < 84) ((float4*)w6p)[tid - 80] = ((const float4*)&g_wpad[W6PAD])[tid - 80];
    __syncthreads();

    // conv4: (8,128)->(4,64), 256 outputs, 1/thread; dual chains
    {
        int o = tid >> 6, p = tid & 63;
        int l = 2 * p;
        float z0a = c4_b[o], z1a = z0a, z0b = 0.f, z1b = 0.f;
        const float4* wo4 = (const float4*)&w4p[o * 64];
        for (int c = 0; c < 8; c += 2) {
            {
                float4 w0 = wo4[c * 2];
                float4 w1 = wo4[c * 2 + 1];
                const float2* pr2 = (const float2*)&s3p[c * 136 + l + 2];
                float2 q0 = pr2[0], q1 = pr2[1], q2 = pr2[2];
                z0a += w0.x * q0.x + w0.y * q0.y + w0.z * q1.x + w0.w * q1.y + w1.x * q2.x;
                z1a += w0.x * q0.y + w0.y * q1.x + w0.z * q1.y + w0.w * q2.x + w1.x * q2.y;
            }
            {
                float4 w0 = wo4[(c + 1) * 2];
                float4 w1 = wo4[(c + 1) * 2 + 1];
                const float2* pr2 = (const float2*)&s3p[(c + 1) * 136 + l + 2];
                float2 q0 = pr2[0], q1 = pr2[1], q2 = pr2[2];
                z0b += w0.x * q0.x + w0.y * q0.y + w0.z * q1.x + w0.w * q1.y + w1.x * q2.x;
                z1b += w0.x * q0.y + w0.y * q1.x + w0.z * q1.y + w0.w * q2.x + w1.x * q2.y;
            }
        }
        float z0 = z0a + z0b, z1 = z1a + z1b;
        s4p[o * 72 + 4 + p] = fmaxf(fmaxf(z0, 0.f), fmaxf(z1, 0.f));
    }
    __syncthreads();

    // conv5: (4,64)->(2,32)
    if (tid < 64) {
        int o = tid >> 5, p = tid & 31;
        int l = 2 * p;
        float z0 = c5_b[o], z1 = z0;
        const float4* wo4 = (const float4*)&w5p[o * 32];
        for (int c = 0; c < 4; c++) {
            float4 w0 = wo4[c * 2];
            float4 w1 = wo4[c * 2 + 1];
            const float2* pr2 = (const float2*)&s4p[c * 72 + l + 2];
            float2 q0 = pr2[0], q1 = pr2[1], q2 = pr2[2];
            z0 += w0.x * q0.x + w0.y * q0.y + w0.z * q1.x + w0.w * q1.y + w1.x * q2.x;
            z1 += w0.x * q0.y + w0.y * q1.x + w0.z * q1.y + w0.w * q2.x + w1.x * q2.y;
        }
        s5p[o * 40 + 4 + p] = fmaxf(fmaxf(z0, 0.f), fmaxf(z1, 0.f));
    }
    __syncthreads();

    // conv6: (2,32)->(1,16)
    if (tid < 16) {
        int l = 2 * tid;
        float z0 = c6_b[0], z1 = z0;
        const float4* wo4 = (const float4*)w6p;
        for (int c = 0; c < 2; c++) {
            float4 w0 = wo4[c * 2];
            float4 w1 = wo4[c * 2 + 1];
            const float2* pr2 = (const float2*)&s5p[c * 40 + l + 2];
            float2 q0 = pr2[0], q1 = pr2[1], q2 = pr2[2];
            z0 += w0.x * q0.x + w0.y * q0.y + w0.z * q1.x + w0.w * q1.y + w1.x * q2.x;
            z1 += w0.x * q0.y + w0.y * q1.x + w0.z * q1.y + w0.w * q2.x + w1.x * q2.y;
        }
        s6[tid] = fmaxf(fmaxf(z0, 0.f), fmaxf(z1, 0.f));
    }
    __syncthreads();

    if (tid == 0) {
        float s = out_b[0];
        #pragma unroll
        for (int j = 0; j < 16; j++) s += s6[j] * out_w[j];
        out[0] = s;
    }
}

extern "C" void kernel_launch(void* const* d_in, const int* in_sizes, int n_in,
                              void* d_out, int out_size) {
    const float* x     = (const float*)d_in[0];
    const float* topo  = (const float*)d_in[1];
    const float* W1    = (const float*)d_in[2];
    const float* W2    = (const float*)d_in[3];
    const float* c1_w  = (const float*)d_in[4];
    const float* c1_b  = (const float*)d_in[5];
    const float* c2_w  = (const float*)d_in[6];
    const float* c2_b  = (const float*)d_in[7];
    const float* c3_w  = (const float*)d_in[8];
    const float* c3_b  = (const float*)d_in[9];
    const float* c4_w  = (const float*)d_in[10];
    const float* c4_b  = (const float*)d_in[11];
    const float* c5_w  = (const float*)d_in[12];
    const float* c5_b  = (const float*)d_in[13];
    const float* c6_w  = (const float*)d_in[14];
    const float* c6_b  = (const float*)d_in[15];
    const float* out_w = (const float*)d_in[16];
    const float* out_b = (const float*)d_in[17];
    float* out = (float*)d_out;

    const int k2_smem = (4096 + 1280 + 1280 + 16384) * 4;   // 92160 B
    cudaFuncSetAttribute(k_y_conv1, cudaFuncAttributeMaxDynamicSharedMemorySize, k2_smem);

    k_attn2<<<NB, 256>>>(x, topo, W1, W2, c1_w, c2_w, c3_w, c4_w, c5_w, c6_w);
    k_y_conv1<<<64, 256, k2_smem>>>(x, c1_b);
    k_conv2<<<16, 256>>>(c2_b);
    k_conv3<<<8, 256>>>(c3_b);
    k_tail2<<<1, 256>>>(c4_b, c5_b, c6_b, out_w, out_b, out);
}